// round 10
// baseline (speedup 1.0000x reference)
#include <cuda_runtime.h>
#include <cstdint>

#define N_EL   19
#define GPC    8                    // graphs per CTA
#define ROWS   (N_EL * GPC)         // 152 valid rows per CTA
#define MPAD   160                  // padded to 10 m16 tiles
#define N_GRAPHS 1800
#define N_NODES  (N_GRAPHS * N_EL)  // 34200
#define C      128
#define GRID   (N_GRAPHS / GPC)     // 225 exact
#define NTHR   512

// smem map (bytes from dynamic base)
#define BOFF   0                    // B tf32: 4 k32-chunks x 256 rows x 128B
#define BCH    32768
#define XOFF   131072               // X tf32: 4 chunks x 160 rows x 128B
#define XCH    20480
#define POFF   131072               // P fp32 (reuses X after MMA): 152 x 528B
#define QOFF   0                    // Q fp32 (reuses B): 152 x 528B
#define PQSTR  528                  // row stride bytes (conflict relief)
#define AOFF   212992               // A 19x20 fp32
#define SMEM_BYTES 214528

// ===========================================================================
// helpers
// ===========================================================================
__device__ __forceinline__ uint32_t s2u(const void* p) {
    uint32_t a;
    asm("{ .reg .u64 t; cvta.to.shared.u64 t, %1; cvt.u32.u64 %0, t; }"
        : "=r"(a) : "l"(p));
    return a;
}
__device__ __forceinline__ uint32_t t32(float f) {
    uint32_t u;
    asm("cvt.rna.tf32.f32 %0, %1;" : "=r"(u) : "f"(f));
    return u;
}
__device__ __forceinline__ void sts16(uint32_t addr, uint4 v) {
    asm volatile("st.shared.v4.b32 [%0], {%1,%2,%3,%4};"
                 :: "r"(addr), "r"(v.x), "r"(v.y), "r"(v.z), "r"(v.w) : "memory");
}
__device__ __forceinline__ void sts8f(uint32_t addr, float a, float b) {
    asm volatile("st.shared.v2.f32 [%0], {%1,%2};"
                 :: "r"(addr), "f"(a), "f"(b) : "memory");
}
__device__ __forceinline__ uint4 lds16(uint32_t addr) {
    uint4 v;
    asm volatile("ld.shared.v4.b32 {%0,%1,%2,%3}, [%4];"
                 : "=r"(v.x), "=r"(v.y), "=r"(v.z), "=r"(v.w) : "r"(addr));
    return v;
}
__device__ __forceinline__ float2 lds8f(uint32_t addr) {
    float2 v;
    asm volatile("ld.shared.v2.f32 {%0,%1}, [%2];"
                 : "=f"(v.x), "=f"(v.y) : "r"(addr));
    return v;
}
__device__ __forceinline__ void mma_tf32(float* d, uint32_t a0, uint32_t a1,
                                         uint32_t a2, uint32_t a3,
                                         uint32_t b0, uint32_t b1) {
    asm volatile(
        "mma.sync.aligned.m16n8k8.row.col.f32.tf32.tf32.f32 "
        "{%0,%1,%2,%3}, {%4,%5,%6,%7}, {%8,%9}, {%0,%1,%2,%3};"
        : "+f"(d[0]), "+f"(d[1]), "+f"(d[2]), "+f"(d[3])
        : "r"(a0), "r"(a1), "r"(a2), "r"(a3), "r"(b0), "r"(b1));
}
// stage 16 consecutive k-values (k16 half 'h' of a k32 chunk) of one row:
// word(k) = (k&3)*8 + (k>>2); 16B granule g stored at g ^ (row & 7).
__device__ __forceinline__ void stage16(uint32_t rowbase, int row, int h,
                                        const float* f) {
#pragma unroll
    for (int cc = 0; cc < 4; cc++) {
        uint4 v = make_uint4(t32(f[cc]), t32(f[cc + 4]),
                             t32(f[cc + 8]), t32(f[cc + 12]));
        sts16(rowbase + (uint32_t)(((cc * 2 + h) ^ (row & 7)) << 4), v);
    }
}

// ===========================================================================
// Fused kernel:
//   per CTA (8 graphs): [P|Q] = X(152x128) @ [Wrel|Wroot]^T  (tf32 MMA)
//   then out = A @ P_g + Q_g + b  (fp32, A shared 19x19 from ew)
// 512 threads: 16 warps (wm 0..1 x wn 0..7), warp tile m80 x n32.
// ===========================================================================
__global__ __launch_bounds__(NTHR, 1) void fused_kernel(
        const float* __restrict__ x,
        const float* __restrict__ ew,
        const float* __restrict__ Wrel,
        const float* __restrict__ brel,
        const float* __restrict__ Wroot,
        float* __restrict__ out) {
    extern __shared__ __align__(16) char smem[];
    const uint32_t sb = s2u(smem);
    float* As = (float*)(smem + AOFF);

    const int tid  = threadIdx.x;
    const int wid  = tid >> 5;
    const int lane = tid & 31;
    const int cta  = blockIdx.x;

    // ---- build A (19x19, shared by all graphs) from edge weights
    for (int e = tid; e < N_EL * N_EL; e += NTHR) {
        const int j = e / N_EL, i = e % N_EL;
        float w = 0.0f;
        if (i != j) {
            const int r = (j < i) ? j : (j - 1);
            w = ew[i * (N_EL - 1) + r];
        }
        As[j * 20 + i] = w;
    }

    // ---- stage X: 1280 units (row 0..159, chunk 0..3, half 0..1)
    for (int u = tid; u < MPAD * 8; u += NTHR) {
        const int row = u >> 3, c = (u >> 1) & 3, h = u & 1;
        float f[16];
        if (row < ROWS) {
            const float4* s4 = (const float4*)(x + (size_t)(cta * ROWS + row) * C
                                               + c * 32 + h * 16);
            *(float4*)&f[0]  = s4[0];
            *(float4*)&f[4]  = s4[1];
            *(float4*)&f[8]  = s4[2];
            *(float4*)&f[12] = s4[3];
        } else {
#pragma unroll
            for (int q = 0; q < 16; q++) f[q] = 0.0f;
        }
        stage16(sb + XOFF + (uint32_t)c * XCH + (uint32_t)row * 128u, row, h, f);
    }

    // ---- stage B = [Wrel; Wroot]: 2048 units (n 0..255, chunk, half)
    for (int u = tid; u < 256 * 8; u += NTHR) {
        const int n = u >> 3, c = (u >> 1) & 3, h = u & 1;
        const float* src = (n < 128) ? Wrel + (size_t)n * C
                                     : Wroot + (size_t)(n - 128) * C;
        const float4* s4 = (const float4*)(src + c * 32 + h * 16);
        float f[16];
        *(float4*)&f[0]  = s4[0];
        *(float4*)&f[4]  = s4[1];
        *(float4*)&f[8]  = s4[2];
        *(float4*)&f[12] = s4[3];
        stage16(sb + BOFF + (uint32_t)c * BCH + (uint32_t)n * 128u, n, h, f);
    }
    __syncthreads();

    // ---- MMA burst: warp tile m80 x n32, K=128
    const int fr = lane >> 2;
    const int fc = lane & 3;
    const int wm = wid >> 3;        // 0..1
    const int wn = wid & 7;         // 0..7

    float acc[5][4][4];
#pragma unroll
    for (int mt = 0; mt < 5; mt++)
#pragma unroll
        for (int n8 = 0; n8 < 4; n8++)
#pragma unroll
            for (int q = 0; q < 4; q++)
                acc[mt][n8][q] = 0.0f;

#pragma unroll
    for (int c = 0; c < 4; c++) {
#pragma unroll
        for (int s = 0; s < 2; s++) {
            uint4 bf[4];
#pragma unroll
            for (int n8 = 0; n8 < 4; n8++) {
                const int nr = wn * 32 + n8 * 8 + fr;
                bf[n8] = lds16(sb + BOFF + (uint32_t)c * BCH + (uint32_t)nr * 128u
                               + (uint32_t)(((fc * 2 + s) ^ (nr & 7)) << 4));
            }
#pragma unroll
            for (int mt = 0; mt < 5; mt++) {
                const int r0 = wm * 80 + mt * 16 + fr;
                const uint32_t xb = sb + XOFF + (uint32_t)c * XCH
                                  + (uint32_t)(((fc * 2 + s) ^ (r0 & 7)) << 4);
                uint4 lo = lds16(xb + (uint32_t)r0 * 128u);
                uint4 hi = lds16(xb + (uint32_t)(r0 + 8) * 128u);
#pragma unroll
                for (int n8 = 0; n8 < 4; n8++) {
                    mma_tf32(acc[mt][n8], lo.x, hi.x, lo.y, hi.y,
                             bf[n8].x, bf[n8].y);
                    mma_tf32(acc[mt][n8], lo.z, hi.z, lo.w, hi.w,
                             bf[n8].z, bf[n8].w);
                }
            }
        }
    }
    __syncthreads();   // X/B smem reads complete -> safe to overwrite with P/Q

    // ---- write accumulators to P (cols 0..127) / Q (cols 128..255)
#pragma unroll
    for (int mt = 0; mt < 5; mt++) {
#pragma unroll
        for (int n8 = 0; n8 < 4; n8++) {
            const int col = wn * 32 + n8 * 8 + fc * 2;
            const uint32_t base = (col < 128)
                ? sb + POFF + (uint32_t)col * 4u
                : sb + QOFF + (uint32_t)(col - 128) * 4u;
#pragma unroll
            for (int half = 0; half < 2; half++) {
                const int r = wm * 80 + mt * 16 + fr + half * 8;
                if (r < ROWS)
                    sts8f(base + (uint32_t)r * PQSTR,
                          acc[mt][n8][half * 2], acc[mt][n8][half * 2 + 1]);
            }
        }
    }
    __syncthreads();

    // ---- phase 2: warp pair per graph; lane owns 2 cols of a 64-col half
    {
        const int g  = wid >> 1;                 // 0..7
        const int ch = (wid & 1) * 64 + lane * 2;
        const float2 bv = *(const float2*)(brel + ch);
        float2 p[N_EL];
#pragma unroll
        for (int i = 0; i < N_EL; i++)
            p[i] = lds8f(sb + POFF + (uint32_t)(g * N_EL + i) * PQSTR
                         + (uint32_t)ch * 4u);
#pragma unroll
        for (int j = 0; j < N_EL; j++) {
            float2 o = lds8f(sb + QOFF + (uint32_t)(g * N_EL + j) * PQSTR
                             + (uint32_t)ch * 4u);
            o.x += bv.x; o.y += bv.y;
#pragma unroll
            for (int i = 0; i < N_EL; i++) {
                const float a = As[j * 20 + i];
                o.x = fmaf(a, p[i].x, o.x);
                o.y = fmaf(a, p[i].y, o.y);
            }
            *(float2*)(out + (size_t)(cta * ROWS + g * N_EL + j) * C + ch) = o;
        }
    }
}

// ===========================================================================
// inputs (metadata order): x, edge_index, edge_weights, W_rel, b_rel, W_root
// ===========================================================================
extern "C" void kernel_launch(void* const* d_in, const int* in_sizes, int n_in,
                              void* d_out, int out_size) {
    const float* x     = (const float*)d_in[0];
    const float* ew    = (const float*)d_in[2];
    const float* Wrel  = (const float*)d_in[3];
    const float* brel  = (const float*)d_in[4];
    const float* Wroot = (const float*)d_in[5];
    float* out = (float*)d_out;

    cudaFuncSetAttribute(fused_kernel, cudaFuncAttributeMaxDynamicSharedMemorySize,
                         SMEM_BYTES);

    fused_kernel<<<GRID, NTHR, SMEM_BYTES>>>(x, ew, Wrel, brel, Wroot, out);
}